// round 1
// baseline (speedup 1.0000x reference)
#include <cuda_runtime.h>
#include <math.h>

#define NN 50000
#define EE 800000
#define CC 64
#define HH 192
#define H3 576
#define EDIM 16
#define GG 2048
#define ETOT (EE + NN)

// ---------------- scratch (device globals; allocation-free rule) ----------------
__device__ float g_x[NN * HH];        // node state
__device__ float g_hW[NN * HH];       // transformed features (also reused as hs in mol phase)
__device__ float g_h[NN * HH];        // GAT output
__device__ float g_gi[NN * H3];
__device__ float g_gh[NN * H3];
__device__ float g_s[NN];
__device__ float g_d[NN];
__device__ float g_ae[EE];
__device__ float g_ew[ETOT];
__device__ float g_sum[NN];
__device__ float g_v[EDIM];
__device__ float g_loopsum[1];
__device__ float g_out[GG * HH];
__device__ float g_hd[GG * HH];
__device__ float g_hmol[GG * HH];
__device__ float g_smol[NN];
__device__ float g_dmol[GG];
__device__ float g_mew[NN];
__device__ float g_msum[GG];

// ---------------- helpers ----------------
__device__ __forceinline__ float warp_sum(float v) {
#pragma unroll
    for (int o = 16; o; o >>= 1) v += __shfl_down_sync(0xffffffffu, v, o);
    return v;
}
__device__ __forceinline__ float sigm(float x) { return 1.f / (1.f + expf(-x)); }

// ---------------- generic kernels ----------------
__global__ void k_zero(float* p, int n) {
    int i = blockIdx.x * 256 + threadIdx.x;
    if (i < n) p[i] = 0.f;
}

// C[M,Nc] = A[M,K] * B[Nc,K]^T  (both K-contiguous). EPI: 0 none, 1 +bias, 2 +bias+lrelu(0.01)
template <int EPI>
__global__ void sgemm_nt(const float* __restrict__ A, const float* __restrict__ B,
                         const float* __restrict__ bias, float* __restrict__ C,
                         int M, int Nc, int K) {
    __shared__ float As[16][64];
    __shared__ float Bs[16][64];
    const int tid = threadIdx.x;             // 256 threads
    const int tx = tid & 15, ty = tid >> 4;  // 16x16
    const int row0 = blockIdx.y * 64;
    const int col0 = blockIdx.x * 64;
    const int lr = tid >> 2;                 // 0..63
    const int lc = (tid & 3) * 4;            // 0,4,8,12

    float acc[4][4] = {};
    for (int k0 = 0; k0 < K; k0 += 16) {
        float4 a4 = make_float4(0.f, 0.f, 0.f, 0.f);
        float4 b4 = make_float4(0.f, 0.f, 0.f, 0.f);
        int ar = row0 + lr;
        if (ar < M) a4 = *(const float4*)(A + (size_t)ar * K + k0 + lc);
        int br = col0 + lr;
        if (br < Nc) b4 = *(const float4*)(B + (size_t)br * K + k0 + lc);
        As[lc + 0][lr] = a4.x; As[lc + 1][lr] = a4.y; As[lc + 2][lr] = a4.z; As[lc + 3][lr] = a4.w;
        Bs[lc + 0][lr] = b4.x; Bs[lc + 1][lr] = b4.y; Bs[lc + 2][lr] = b4.z; Bs[lc + 3][lr] = b4.w;
        __syncthreads();
#pragma unroll
        for (int k = 0; k < 16; k++) {
            float4 av = *(const float4*)&As[k][ty * 4];
            float4 bv = *(const float4*)&Bs[k][tx * 4];
            float aa[4] = {av.x, av.y, av.z, av.w};
            float bb[4] = {bv.x, bv.y, bv.z, bv.w};
#pragma unroll
            for (int i = 0; i < 4; i++)
#pragma unroll
                for (int j = 0; j < 4; j++) acc[i][j] += aa[i] * bb[j];
        }
        __syncthreads();
    }
#pragma unroll
    for (int i = 0; i < 4; i++) {
        int r = row0 + ty * 4 + i;
        if (r >= M) continue;
#pragma unroll
        for (int j = 0; j < 4; j++) {
            int c = col0 + tx * 4 + j;
            float v = acc[i][j];
            if (EPI >= 1) v += bias[c];
            if (EPI == 2) v = v > 0.f ? v : 0.01f * v;
            C[(size_t)r * Nc + c] = v;
        }
    }
}

// v[j] = sum_k att_e[k] * We[k,j]; also zero loopsum
__global__ void k_v(const float* __restrict__ We, const float* __restrict__ atte) {
    int j = threadIdx.x;
    if (j < EDIM) {
        float s = 0.f;
        for (int k = 0; k < HH; k++) s += atte[k] * We[k * EDIM + j];
        g_v[j] = s;
    }
    if (j == 0) g_loopsum[0] = 0.f;
}

// per-edge alpha_e = dot(edge_attr[e], v); accumulate sum for the mean-loop term
__global__ void k_ae(const float* __restrict__ attr) {
    __shared__ float sv[EDIM];
    __shared__ float red[256];
    if (threadIdx.x < EDIM) sv[threadIdx.x] = g_v[threadIdx.x];
    __syncthreads();
    int e = blockIdx.x * 256 + threadIdx.x;
    float a = 0.f;
    if (e < EE) {
        const float* p = attr + (size_t)e * EDIM;
#pragma unroll
        for (int j = 0; j < EDIM; j++) a += p[j] * sv[j];
        g_ae[e] = a;
    }
    red[threadIdx.x] = a;
    __syncthreads();
    for (int st = 128; st; st >>= 1) {
        if (threadIdx.x < st) red[threadIdx.x] += red[threadIdx.x + st];
        __syncthreads();
    }
    if (threadIdx.x == 0) atomicAdd(g_loopsum, red[0]);
}

// warp-per-row dual dot product with attention vectors
__global__ void k_rowdot2(const float* __restrict__ A, const float* __restrict__ u,
                          const float* __restrict__ w, float* __restrict__ ou,
                          float* __restrict__ ow, int rows) {
    int gw = (blockIdx.x * blockDim.x + threadIdx.x) >> 5;
    int lane = threadIdx.x & 31;
    if (gw >= rows) return;
    const float* a = A + (size_t)gw * HH;
    float s1 = 0.f, s2 = 0.f;
    for (int k = lane; k < HH; k += 32) {
        float v = a[k];
        s1 += v * u[k];
        if (w) s2 += v * w[k];
    }
    s1 = warp_sum(s1);
    if (w) s2 = warp_sum(s2);
    if (lane == 0) {
        ou[gw] = s1;
        if (w) ow[gw] = s2;
    }
}

__global__ void k_edge1_c0(const int* __restrict__ src, const int* __restrict__ dst) {
    int idx = blockIdx.x * 256 + threadIdx.x;
    if (idx >= ETOT) return;
    int dd;
    float a;
    if (idx < EE) {
        int ss = src[idx];
        dd = dst[idx];
        a = g_s[ss] + g_d[dd] + g_ae[idx];
    } else {
        int i = idx - EE;
        dd = i;
        a = g_s[i] + g_d[i] + g_loopsum[0] * (1.0f / EE);
    }
    a = a >= 0.f ? a : 0.2f * a;
    float e = expf(a);
    g_ew[idx] = e;
    atomicAdd(&g_sum[dd], e);
}

__global__ void k_edge1_plain(const int* __restrict__ src, const int* __restrict__ dst) {
    int idx = blockIdx.x * 256 + threadIdx.x;
    if (idx >= EE) return;
    float a = g_s[src[idx]] + g_d[dst[idx]];
    a = a >= 0.f ? a : 0.01f * a;
    float e = expf(a);
    g_ew[idx] = e;
    atomicAdd(&g_sum[dst[idx]], e);
}

template <bool SELF>
__global__ void k_edge2(const int* __restrict__ src, const int* __restrict__ dst, int etot) {
    int gw = (blockIdx.x * blockDim.x + threadIdx.x) >> 5;
    int lane = threadIdx.x & 31;
    if (gw >= etot) return;
    int ss, dd;
    if (SELF && gw >= EE) {
        ss = dd = gw - EE;
    } else {
        ss = src[gw];
        dd = dst[gw];
    }
    float w = g_ew[gw] / (g_sum[dd] + 1e-16f);
    const float* hs = g_hW + (size_t)ss * HH;
    float* o = g_h + (size_t)dd * HH;
    for (int k = lane; k < HH; k += 32) atomicAdd(&o[k], w * hs[k]);
}

__global__ void k_elu(float* __restrict__ h, const float* __restrict__ b, int rows) {
    int idx = blockIdx.x * 256 + threadIdx.x;
    if (idx >= rows * HH) return;
    int j = idx % HH;
    float v = h[idx] + b[j];
    h[idx] = v > 0.f ? v : expm1f(v);
}

__global__ void k_gru(const float* __restrict__ gi, const float* __restrict__ gh,
                      float* __restrict__ x, int rows) {
    int idx = blockIdx.x * 256 + threadIdx.x;
    if (idx >= rows * HH) return;
    int i = idx / HH, j = idx % HH;
    const float* a = gi + (size_t)i * H3;
    const float* b = gh + (size_t)i * H3;
    float r = sigm(a[j] + b[j]);
    float z = sigm(a[HH + j] + b[HH + j]);
    float n = tanhf(a[2 * HH + j] + r * b[2 * HH + j]);
    float o = (1.f - z) * n + z * x[idx];
    x[idx] = o > 0.f ? o : 0.f;
}

__global__ void k_pool(const int* __restrict__ batch) {
    int idx = blockIdx.x * 256 + threadIdx.x;
    if (idx >= NN * HH) return;
    int i = idx / HH, j = idx % HH;
    atomicAdd(&g_out[batch[i] * HH + j], g_x[idx]);
}

__global__ void k_relu_inplace(float* p, int n) {
    int i = blockIdx.x * 256 + threadIdx.x;
    if (i < n) p[i] = p[i] > 0.f ? p[i] : 0.f;
}

__global__ void k_mol1(const int* __restrict__ batch) {
    int i = blockIdx.x * 256 + threadIdx.x;
    if (i >= NN) return;
    float a = g_smol[i] + g_dmol[batch[i]];
    a = a >= 0.f ? a : 0.01f * a;
    float e = expf(a);
    g_mew[i] = e;
    atomicAdd(&g_msum[batch[i]], e);
}

__global__ void k_mol2(const int* __restrict__ batch) {
    int gw = (blockIdx.x * blockDim.x + threadIdx.x) >> 5;
    int lane = threadIdx.x & 31;
    if (gw >= NN) return;
    int b = batch[gw];
    float w = g_mew[gw] / (g_msum[b] + 1e-16f);
    const float* hs = g_hW + (size_t)gw * HH;
    float* o = g_hmol + (size_t)b * HH;
    for (int k = lane; k < HH; k += 32) atomicAdd(&o[k], w * hs[k]);
}

__global__ void k_final(const float* __restrict__ W, const float* __restrict__ b,
                        float* __restrict__ out) {
    int gw = (blockIdx.x * blockDim.x + threadIdx.x) >> 5;
    int lane = threadIdx.x & 31;
    if (gw >= GG) return;
    float s = 0.f;
    for (int k = lane; k < HH; k += 32) s += g_out[gw * HH + k] * W[k];
    s = warp_sum(s);
    if (lane == 0) out[gw] = s + b[0];
}

// ---------------- host ----------------
static inline int cdiv(int a, int b) { return (a + b - 1) / b; }

extern "C" void kernel_launch(void* const* d_in, const int* in_sizes, int n_in,
                              void* d_out, int out_size) {
    const float* x_in = (const float*)d_in[0];
    const int* eidx = (const int*)d_in[1];
    const float* eattr = (const float*)d_in[2];
    const int* batch = (const int*)d_in[3];
    const float* lin1_W = (const float*)d_in[4];
    const float* lin1_b = (const float*)d_in[5];
    const float* conv0_W = (const float*)d_in[6];
    const float* conv0_att_s = (const float*)d_in[7];
    const float* conv0_att_d = (const float*)d_in[8];
    const float* conv0_We = (const float*)d_in[9];
    const float* conv0_att_e = (const float*)d_in[10];
    const float* conv0_b = (const float*)d_in[11];
    const float* convs_W = (const float*)d_in[12];
    const float* convs_att_s = (const float*)d_in[13];
    const float* convs_att_d = (const float*)d_in[14];
    const float* convs_b = (const float*)d_in[15];
    const float* gru_Wih = (const float*)d_in[16];
    const float* gru_Whh = (const float*)d_in[17];
    const float* gru_bih = (const float*)d_in[18];
    const float* gru_bhh = (const float*)d_in[19];
    const float* mol_Wsrc = (const float*)d_in[20];
    const float* mol_Wdst = (const float*)d_in[21];
    const float* mol_att_s = (const float*)d_in[22];
    const float* mol_att_d = (const float*)d_in[23];
    const float* mol_b = (const float*)d_in[24];
    const float* mgru_Wih = (const float*)d_in[25];
    const float* mgru_Whh = (const float*)d_in[26];
    const float* mgru_bih = (const float*)d_in[27];
    const float* mgru_bhh = (const float*)d_in[28];
    const float* lin2_W = (const float*)d_in[29];
    const float* lin2_b = (const float*)d_in[30];

    const int* src = eidx;
    const int* dst = eidx + EE;

    float *px, *phW, *ph, *pgi, *pgh, *ps, *pd, *psum, *pout, *phd, *phmol, *psmol, *pdmol, *pmsum;
    cudaGetSymbolAddress((void**)&px, g_x);
    cudaGetSymbolAddress((void**)&phW, g_hW);
    cudaGetSymbolAddress((void**)&ph, g_h);
    cudaGetSymbolAddress((void**)&pgi, g_gi);
    cudaGetSymbolAddress((void**)&pgh, g_gh);
    cudaGetSymbolAddress((void**)&ps, g_s);
    cudaGetSymbolAddress((void**)&pd, g_d);
    cudaGetSymbolAddress((void**)&psum, g_sum);
    cudaGetSymbolAddress((void**)&pout, g_out);
    cudaGetSymbolAddress((void**)&phd, g_hd);
    cudaGetSymbolAddress((void**)&phmol, g_hmol);
    cudaGetSymbolAddress((void**)&psmol, g_smol);
    cudaGetSymbolAddress((void**)&pdmol, g_dmol);
    cudaGetSymbolAddress((void**)&pmsum, g_msum);

    auto gemm = [&](const float* A, const float* B, const float* bias, float* C,
                    int M, int Nc, int K, int epi) {
        dim3 grid(Nc / 64, cdiv(M, 64));
        if (epi == 0)
            sgemm_nt<0><<<grid, 256>>>(A, B, bias, C, M, Nc, K);
        else if (epi == 1)
            sgemm_nt<1><<<grid, 256>>>(A, B, bias, C, M, Nc, K);
        else
            sgemm_nt<2><<<grid, 256>>>(A, B, bias, C, M, Nc, K);
    };

    // ---- lin1 + leaky_relu(0.01) ----
    gemm(x_in, lin1_W, lin1_b, px, NN, HH, CC, 2);

    // ---- conv0 (edge features + self loops, slope 0.2) ----
    k_v<<<1, 32>>>(conv0_We, conv0_att_e);
    k_ae<<<cdiv(EE, 256), 256>>>(eattr);
    gemm(px, conv0_W, nullptr, phW, NN, HH, HH, 0);
    k_rowdot2<<<cdiv(NN * 32, 256), 256>>>(phW, conv0_att_s, conv0_att_d, ps, pd, NN);
    k_zero<<<cdiv(NN, 256), 256>>>(psum, NN);
    k_zero<<<cdiv(NN * HH, 256), 256>>>(ph, NN * HH);
    k_edge1_c0<<<cdiv(ETOT, 256), 256>>>(src, dst);
    k_edge2<true><<<cdiv(ETOT * 32, 256), 256>>>(src, dst, ETOT);
    k_elu<<<cdiv(NN * HH, 256), 256>>>(ph, conv0_b, NN);
    gemm(ph, gru_Wih, gru_bih, pgi, NN, H3, HH, 1);
    gemm(px, gru_Whh, gru_bhh, pgh, NN, H3, HH, 1);
    k_gru<<<cdiv(NN * HH, 256), 256>>>(pgi, pgh, px, NN);

    // ---- remaining atom conv layers (slope 0.01) ----
    for (int l = 0; l < 2; l++) {
        gemm(px, convs_W + (size_t)l * HH * HH, nullptr, phW, NN, HH, HH, 0);
        k_rowdot2<<<cdiv(NN * 32, 256), 256>>>(phW, convs_att_s + l * HH,
                                               convs_att_d + l * HH, ps, pd, NN);
        k_zero<<<cdiv(NN, 256), 256>>>(psum, NN);
        k_zero<<<cdiv(NN * HH, 256), 256>>>(ph, NN * HH);
        k_edge1_plain<<<cdiv(EE, 256), 256>>>(src, dst);
        k_edge2<false><<<cdiv(EE * 32, 256), 256>>>(src, dst, EE);
        k_elu<<<cdiv(NN * HH, 256), 256>>>(ph, convs_b + l * HH, NN);
        gemm(ph, gru_Wih + (size_t)(l + 1) * H3 * HH, gru_bih + (l + 1) * H3, pgi, NN, H3, HH, 1);
        gemm(px, gru_Whh + (size_t)(l + 1) * H3 * HH, gru_bhh + (l + 1) * H3, pgh, NN, H3, HH, 1);
        k_gru<<<cdiv(NN * HH, 256), 256>>>(pgi, pgh, px, NN);
    }

    // ---- molecule readout ----
    k_zero<<<cdiv(GG * HH, 256), 256>>>(pout, GG * HH);
    k_pool<<<cdiv(NN * HH, 256), 256>>>(batch);
    k_relu_inplace<<<cdiv(GG * HH, 256), 256>>>(pout, GG * HH);
    gemm(px, mol_Wsrc, nullptr, phW, NN, HH, HH, 0);  // hs lives in g_hW
    k_rowdot2<<<cdiv(NN * 32, 256), 256>>>(phW, mol_att_s, nullptr, psmol, nullptr, NN);

    for (int t = 0; t < 2; t++) {
        gemm(pout, mol_Wdst, nullptr, phd, GG, HH, HH, 0);
        k_rowdot2<<<cdiv(GG * 32, 256), 256>>>(phd, mol_att_d, nullptr, pdmol, nullptr, GG);
        k_zero<<<cdiv(GG, 256), 256>>>(pmsum, GG);
        k_zero<<<cdiv(GG * HH, 256), 256>>>(phmol, GG * HH);
        k_mol1<<<cdiv(NN, 256), 256>>>(batch);
        k_mol2<<<cdiv(NN * 32, 256), 256>>>(batch);
        k_elu<<<cdiv(GG * HH, 256), 256>>>(phmol, mol_b, GG);
        gemm(phmol, mgru_Wih, mgru_bih, pgi, GG, H3, HH, 1);
        gemm(pout, mgru_Whh, mgru_bhh, pgh, GG, H3, HH, 1);
        k_gru<<<cdiv(GG * HH, 256), 256>>>(pgi, pgh, pout, GG);
    }

    k_final<<<cdiv(GG * 32, 256), 256>>>(lin2_W, lin2_b, (float*)d_out);
}

// round 2
// speedup vs baseline: 1.2652x; 1.2652x over previous
#include <cuda_runtime.h>
#include <math.h>

#define NN 50000
#define EE 800000
#define CC 64
#define HH 192
#define H3 576
#define EDIM 16
#define GG 2048
#define ETOT (EE + NN)

// ---------------- scratch (device globals; allocation-free rule) ----------------
__device__ float g_x[NN * HH];
__device__ float g_hW[NN * HH];
__device__ float g_h[NN * HH];
__device__ float g_gi[NN * H3];
__device__ float g_gh[NN * H3];
__device__ float g_s[NN];
__device__ float g_d[NN];
__device__ float g_ae[EE];
__device__ float g_ew[ETOT];
__device__ float g_sum[NN];
__device__ float g_v[EDIM];
__device__ float g_loopsum[1];
__device__ float g_out[GG * HH];
__device__ float g_hd[GG * HH];
__device__ float g_hmol[GG * HH];
__device__ float g_smol[NN];
__device__ float g_dmol[GG];
__device__ float g_mew[NN];
__device__ float g_msum[GG];

// ---------------- helpers ----------------
__device__ __forceinline__ float warp_sum(float v) {
#pragma unroll
    for (int o = 16; o; o >>= 1) v += __shfl_down_sync(0xffffffffu, v, o);
    return v;
}
__device__ __forceinline__ float sigm(float x) { return 1.f / (1.f + expf(-x)); }

__device__ __forceinline__ void red4(float4* p, float4 v) {
    asm volatile("red.global.add.v4.f32 [%0], {%1,%2,%3,%4};"
                 :: "l"(p), "f"(v.x), "f"(v.y), "f"(v.z), "f"(v.w)
                 : "memory");
}

__global__ void k_zero(float* p, int n) {
    int i = blockIdx.x * 256 + threadIdx.x;
    if (i < n) p[i] = 0.f;
}

// ================ SGEMM: C[M,Nc] = A[M,K] * B[Nc,K]^T ================
// BM=256, BN=64, BK=16, 256 threads, 8x8 microtile, double buffered,
// XOR-swizzled float4 groups: conflict-free LDS and STS.
// EPI: 0 none, 1 +bias, 2 +bias+lrelu(0.01)
template <int EPI>
__global__ void __launch_bounds__(256, 2)
sgemm_nt2(const float* __restrict__ A, const float* __restrict__ B,
          const float* __restrict__ bias, float* __restrict__ C,
          int M, int Nc, int K) {
    __shared__ float As[2][16][256];
    __shared__ float Bs[2][16][64];
    const int tid = threadIdx.x;
    const int tx = tid & 7;    // col group 0..7
    const int ty = tid >> 3;   // row group 0..31
    const int row0 = blockIdx.y * 256;
    const int col0 = blockIdx.x * 64;

    const int la_r = tid >> 2;        // 0..63 (A rows: +0,+64,+128,+192)
    const int l_k = (tid & 3) * 4;    // k offset 0,4,8,12
    const int lsk = l_k >> 2;         // swizzle const for this loader thread

    float a_reg[4][4];
    float b_reg[4];
    float acc[8][8];
#pragma unroll
    for (int i = 0; i < 8; i++)
#pragma unroll
        for (int j = 0; j < 8; j++) acc[i][j] = 0.f;

    const int nchunks = K >> 4;

#define LDG_CHUNK(kc)                                                          \
    {                                                                          \
        int kbase = (kc) * 16 + l_k;                                           \
        _Pragma("unroll") for (int r = 0; r < 4; r++) {                        \
            int row = row0 + la_r + r * 64;                                    \
            float4 v = make_float4(0.f, 0.f, 0.f, 0.f);                        \
            if (row < M) v = *(const float4*)(A + (size_t)row * K + kbase);    \
            a_reg[r][0] = v.x; a_reg[r][1] = v.y;                              \
            a_reg[r][2] = v.z; a_reg[r][3] = v.w;                              \
        }                                                                      \
        float4 bv = *(const float4*)(B + (size_t)(col0 + la_r) * K + kbase);   \
        b_reg[0] = bv.x; b_reg[1] = bv.y; b_reg[2] = bv.z; b_reg[3] = bv.w;    \
    }

#define STS_CHUNK(buf)                                                         \
    {                                                                          \
        _Pragma("unroll") for (int r = 0; r < 4; r++) {                        \
            int m = la_r + r * 64;                                             \
            int mg = (m >> 2) ^ lsk;  /* XOR low 2 bits only (lsk<4) */        \
            int col = ((m >> 2) & ~3) == (mg & ~3) ? 0 : 0;                    \
            (void)col;                                                         \
            int base = (((m >> 2) & ~3) | (mg & 3)) * 4 + (m & 3);             \
            _Pragma("unroll") for (int j = 0; j < 4; j++)                      \
                As[buf][l_k + j][base] = a_reg[r][j];                          \
        }                                                                      \
        {                                                                      \
            int n = la_r;                                                      \
            int base = ((((n >> 2) & ~3) | (((n >> 2) ^ lsk) & 3)) * 4) + (n & 3); \
            _Pragma("unroll") for (int j = 0; j < 4; j++)                      \
                Bs[buf][l_k + j][base] = b_reg[j];                             \
        }                                                                      \
    }

#define COMPUTE_CHUNK(buf)                                                     \
    {                                                                          \
        _Pragma("unroll") for (int k = 0; k < 16; k++) {                       \
            int sk = k >> 2;                                                   \
            int g0 = ((ty * 2) & ~3) | (((ty * 2) ^ sk) & 3);                  \
            int g1 = ((ty * 2 + 1) & ~3) | (((ty * 2 + 1) ^ sk) & 3);          \
            int gb = (tx ^ sk) & 7; /* tx<8, sk<4 */                           \
            float4 a0 = *(const float4*)&As[buf][k][g0 << 2];                  \
            float4 a1 = *(const float4*)&As[buf][k][g1 << 2];                  \
            float4 b0 = *(const float4*)&Bs[buf][k][gb << 2];                  \
            float4 b1 = *(const float4*)&Bs[buf][k][(gb + 8) << 2];            \
            float av[8] = {a0.x, a0.y, a0.z, a0.w, a1.x, a1.y, a1.z, a1.w};    \
            float bv[8] = {b0.x, b0.y, b0.z, b0.w, b1.x, b1.y, b1.z, b1.w};    \
            _Pragma("unroll") for (int i = 0; i < 8; i++)                      \
                _Pragma("unroll") for (int j = 0; j < 8; j++)                  \
                    acc[i][j] += av[i] * bv[j];                                \
        }                                                                      \
    }

    LDG_CHUNK(0);
    STS_CHUNK(0);
    __syncthreads();
    for (int c = 0; c < nchunks; c++) {
        int buf = c & 1;
        if (c + 1 < nchunks) LDG_CHUNK(c + 1);
        COMPUTE_CHUNK(buf);
        if (c + 1 < nchunks) {
            STS_CHUNK(buf ^ 1);
            __syncthreads();
        }
    }

    // epilogue: thread's logical cols: tx (groups tx, tx+8) -> n = tx*4+j and 32+tx*4+j
    // wait: group g covers cols g*4..g*4+3; groups are tx and tx+8.
#pragma unroll
    for (int i = 0; i < 8; i++) {
        int row = row0 + ty * 8 + i;
        if (row >= M) continue;
#pragma unroll
        for (int half = 0; half < 2; half++) {
            int c0 = col0 + (tx + half * 8) * 4;
            float4 v;
            v.x = acc[i][half * 4 + 0];
            v.y = acc[i][half * 4 + 1];
            v.z = acc[i][half * 4 + 2];
            v.w = acc[i][half * 4 + 3];
            if (EPI >= 1) {
                v.x += bias[c0 + 0]; v.y += bias[c0 + 1];
                v.z += bias[c0 + 2]; v.w += bias[c0 + 3];
            }
            if (EPI == 2) {
                v.x = v.x > 0.f ? v.x : 0.01f * v.x;
                v.y = v.y > 0.f ? v.y : 0.01f * v.y;
                v.z = v.z > 0.f ? v.z : 0.01f * v.z;
                v.w = v.w > 0.f ? v.w : 0.01f * v.w;
            }
            *(float4*)(C + (size_t)row * Nc + c0) = v;
        }
    }
}

// ---------------- attention prep ----------------
__global__ void k_v(const float* __restrict__ We, const float* __restrict__ atte) {
    int j = threadIdx.x;
    if (j < EDIM) {
        float s = 0.f;
        for (int k = 0; k < HH; k++) s += atte[k] * We[k * EDIM + j];
        g_v[j] = s;
    }
    if (j == 0) g_loopsum[0] = 0.f;
}

__global__ void k_ae(const float* __restrict__ attr) {
    __shared__ float sv[EDIM];
    __shared__ float red[256];
    if (threadIdx.x < EDIM) sv[threadIdx.x] = g_v[threadIdx.x];
    __syncthreads();
    int e = blockIdx.x * 256 + threadIdx.x;
    float a = 0.f;
    if (e < EE) {
        const float* p = attr + (size_t)e * EDIM;
#pragma unroll
        for (int j = 0; j < EDIM; j++) a += p[j] * sv[j];
        g_ae[e] = a;
    }
    red[threadIdx.x] = a;
    __syncthreads();
    for (int st = 128; st; st >>= 1) {
        if (threadIdx.x < st) red[threadIdx.x] += red[threadIdx.x + st];
        __syncthreads();
    }
    if (threadIdx.x == 0) atomicAdd(g_loopsum, red[0]);
}

__global__ void k_rowdot2(const float* __restrict__ A, const float* __restrict__ u,
                          const float* __restrict__ w, float* __restrict__ ou,
                          float* __restrict__ ow, int rows) {
    int gw = (blockIdx.x * blockDim.x + threadIdx.x) >> 5;
    int lane = threadIdx.x & 31;
    if (gw >= rows) return;
    const float* a = A + (size_t)gw * HH;
    float s1 = 0.f, s2 = 0.f;
    for (int k = lane; k < HH; k += 32) {
        float v = a[k];
        s1 += v * u[k];
        if (w) s2 += v * w[k];
    }
    s1 = warp_sum(s1);
    if (w) s2 = warp_sum(s2);
    if (lane == 0) {
        ou[gw] = s1;
        if (w) ow[gw] = s2;
    }
}

__global__ void k_edge1_c0(const int* __restrict__ src, const int* __restrict__ dst) {
    int idx = blockIdx.x * 256 + threadIdx.x;
    if (idx >= ETOT) return;
    int dd;
    float a;
    if (idx < EE) {
        int ss = src[idx];
        dd = dst[idx];
        a = g_s[ss] + g_d[dd] + g_ae[idx];
    } else {
        int i = idx - EE;
        dd = i;
        a = g_s[i] + g_d[i] + g_loopsum[0] * (1.0f / EE);
    }
    a = a >= 0.f ? a : 0.2f * a;
    float e = expf(a);
    g_ew[idx] = e;
    atomicAdd(&g_sum[dd], e);
}

__global__ void k_edge1_plain(const int* __restrict__ src, const int* __restrict__ dst) {
    int idx = blockIdx.x * 256 + threadIdx.x;
    if (idx >= EE) return;
    float a = g_s[src[idx]] + g_d[dst[idx]];
    a = a >= 0.f ? a : 0.01f * a;
    float e = expf(a);
    g_ew[idx] = e;
    atomicAdd(&g_sum[dst[idx]], e);
}

// warp per edge, float4 vector reductions (48 float4 per row)
template <bool SELF>
__global__ void k_edge2(const int* __restrict__ src, const int* __restrict__ dst, int etot) {
    int gw = (blockIdx.x * blockDim.x + threadIdx.x) >> 5;
    int lane = threadIdx.x & 31;
    if (gw >= etot) return;
    int ss = 0, dd = 0;
    float w = 0.f;
    if (lane == 0) {
        if (SELF && gw >= EE) {
            ss = dd = gw - EE;
        } else {
            ss = src[gw];
            dd = dst[gw];
        }
        w = g_ew[gw] / (g_sum[dd] + 1e-16f);
    }
    ss = __shfl_sync(0xffffffffu, ss, 0);
    dd = __shfl_sync(0xffffffffu, dd, 0);
    w = __shfl_sync(0xffffffffu, w, 0);
    const float4* hs = (const float4*)(g_hW + (size_t)ss * HH);
    float4* o = (float4*)(g_h + (size_t)dd * HH);
    float4 v = hs[lane];
    red4(o + lane, make_float4(w * v.x, w * v.y, w * v.z, w * v.w));
    if (lane < 16) {
        float4 v2 = hs[lane + 32];
        red4(o + lane + 32, make_float4(w * v2.x, w * v2.y, w * v2.z, w * v2.w));
    }
}

__global__ void k_elu(float* __restrict__ h, const float* __restrict__ b, int rows) {
    int idx = blockIdx.x * 256 + threadIdx.x;
    if (idx >= rows * HH) return;
    int j = idx % HH;
    float v = h[idx] + b[j];
    h[idx] = v > 0.f ? v : expm1f(v);
}

__global__ void k_gru(const float* __restrict__ gi, const float* __restrict__ gh,
                      float* __restrict__ x, int rows) {
    int idx = blockIdx.x * 256 + threadIdx.x;
    if (idx >= rows * HH) return;
    int i = idx / HH, j = idx % HH;
    const float* a = gi + (size_t)i * H3;
    const float* b = gh + (size_t)i * H3;
    float r = sigm(a[j] + b[j]);
    float z = sigm(a[HH + j] + b[HH + j]);
    float n = tanhf(a[2 * HH + j] + r * b[2 * HH + j]);
    float o = (1.f - z) * n + z * x[idx];
    x[idx] = o > 0.f ? o : 0.f;
}

__global__ void k_pool(const int* __restrict__ batch) {
    int idx = blockIdx.x * 256 + threadIdx.x;
    if (idx >= NN * 48) return;
    int i = idx / 48, j = idx % 48;
    float4 v = ((const float4*)(g_x + (size_t)i * HH))[j];
    red4(((float4*)(g_out + (size_t)batch[i] * HH)) + j, v);
}

__global__ void k_relu_inplace(float* p, int n) {
    int i = blockIdx.x * 256 + threadIdx.x;
    if (i < n) p[i] = p[i] > 0.f ? p[i] : 0.f;
}

__global__ void k_mol1(const int* __restrict__ batch) {
    int i = blockIdx.x * 256 + threadIdx.x;
    if (i >= NN) return;
    float a = g_smol[i] + g_dmol[batch[i]];
    a = a >= 0.f ? a : 0.01f * a;
    float e = expf(a);
    g_mew[i] = e;
    atomicAdd(&g_msum[batch[i]], e);
}

__global__ void k_mol2(const int* __restrict__ batch) {
    int gw = (blockIdx.x * blockDim.x + threadIdx.x) >> 5;
    int lane = threadIdx.x & 31;
    if (gw >= NN) return;
    int b = 0;
    float w = 0.f;
    if (lane == 0) {
        b = batch[gw];
        w = g_mew[gw] / (g_msum[b] + 1e-16f);
    }
    b = __shfl_sync(0xffffffffu, b, 0);
    w = __shfl_sync(0xffffffffu, w, 0);
    const float4* hs = (const float4*)(g_hW + (size_t)gw * HH);
    float4* o = (float4*)(g_hmol + (size_t)b * HH);
    float4 v = hs[lane];
    red4(o + lane, make_float4(w * v.x, w * v.y, w * v.z, w * v.w));
    if (lane < 16) {
        float4 v2 = hs[lane + 32];
        red4(o + lane + 32, make_float4(w * v2.x, w * v2.y, w * v2.z, w * v2.w));
    }
}

__global__ void k_final(const float* __restrict__ W, const float* __restrict__ b,
                        float* __restrict__ out) {
    int gw = (blockIdx.x * blockDim.x + threadIdx.x) >> 5;
    int lane = threadIdx.x & 31;
    if (gw >= GG) return;
    float s = 0.f;
    for (int k = lane; k < HH; k += 32) s += g_out[gw * HH + k] * W[k];
    s = warp_sum(s);
    if (lane == 0) out[gw] = s + b[0];
}

// ---------------- host ----------------
static inline int cdiv(int a, int b) { return (a + b - 1) / b; }

extern "C" void kernel_launch(void* const* d_in, const int* in_sizes, int n_in,
                              void* d_out, int out_size) {
    const float* x_in = (const float*)d_in[0];
    const int* eidx = (const int*)d_in[1];
    const float* eattr = (const float*)d_in[2];
    const int* batch = (const int*)d_in[3];
    const float* lin1_W = (const float*)d_in[4];
    const float* lin1_b = (const float*)d_in[5];
    const float* conv0_W = (const float*)d_in[6];
    const float* conv0_att_s = (const float*)d_in[7];
    const float* conv0_att_d = (const float*)d_in[8];
    const float* conv0_We = (const float*)d_in[9];
    const float* conv0_att_e = (const float*)d_in[10];
    const float* conv0_b = (const float*)d_in[11];
    const float* convs_W = (const float*)d_in[12];
    const float* convs_att_s = (const float*)d_in[13];
    const float* convs_att_d = (const float*)d_in[14];
    const float* convs_b = (const float*)d_in[15];
    const float* gru_Wih = (const float*)d_in[16];
    const float* gru_Whh = (const float*)d_in[17];
    const float* gru_bih = (const float*)d_in[18];
    const float* gru_bhh = (const float*)d_in[19];
    const float* mol_Wsrc = (const float*)d_in[20];
    const float* mol_Wdst = (const float*)d_in[21];
    const float* mol_att_s = (const float*)d_in[22];
    const float* mol_att_d = (const float*)d_in[23];
    const float* mol_b = (const float*)d_in[24];
    const float* mgru_Wih = (const float*)d_in[25];
    const float* mgru_Whh = (const float*)d_in[26];
    const float* mgru_bih = (const float*)d_in[27];
    const float* mgru_bhh = (const float*)d_in[28];
    const float* lin2_W = (const float*)d_in[29];
    const float* lin2_b = (const float*)d_in[30];

    const int* src = eidx;
    const int* dst = eidx + EE;

    float *px, *phW, *ph, *pgi, *pgh, *ps, *pd, *psum, *pout, *phd, *phmol, *psmol, *pdmol, *pmsum;
    cudaGetSymbolAddress((void**)&px, g_x);
    cudaGetSymbolAddress((void**)&phW, g_hW);
    cudaGetSymbolAddress((void**)&ph, g_h);
    cudaGetSymbolAddress((void**)&pgi, g_gi);
    cudaGetSymbolAddress((void**)&pgh, g_gh);
    cudaGetSymbolAddress((void**)&ps, g_s);
    cudaGetSymbolAddress((void**)&pd, g_d);
    cudaGetSymbolAddress((void**)&psum, g_sum);
    cudaGetSymbolAddress((void**)&pout, g_out);
    cudaGetSymbolAddress((void**)&phd, g_hd);
    cudaGetSymbolAddress((void**)&phmol, g_hmol);
    cudaGetSymbolAddress((void**)&psmol, g_smol);
    cudaGetSymbolAddress((void**)&pdmol, g_dmol);
    cudaGetSymbolAddress((void**)&pmsum, g_msum);

    auto gemm = [&](const float* A, const float* B, const float* bias, float* C,
                    int M, int Nc, int K, int epi) {
        dim3 grid(Nc / 64, cdiv(M, 256));
        if (epi == 0)
            sgemm_nt2<0><<<grid, 256>>>(A, B, bias, C, M, Nc, K);
        else if (epi == 1)
            sgemm_nt2<1><<<grid, 256>>>(A, B, bias, C, M, Nc, K);
        else
            sgemm_nt2<2><<<grid, 256>>>(A, B, bias, C, M, Nc, K);
    };

    // ---- lin1 + leaky_relu(0.01) ----
    gemm(x_in, lin1_W, lin1_b, px, NN, HH, CC, 2);

    // ---- conv0 (edge features + self loops, slope 0.2) ----
    k_v<<<1, 32>>>(conv0_We, conv0_att_e);
    k_ae<<<cdiv(EE, 256), 256>>>(eattr);
    gemm(px, conv0_W, nullptr, phW, NN, HH, HH, 0);
    k_rowdot2<<<cdiv(NN * 32, 256), 256>>>(phW, conv0_att_s, conv0_att_d, ps, pd, NN);
    k_zero<<<cdiv(NN, 256), 256>>>(psum, NN);
    k_zero<<<cdiv(NN * HH, 256), 256>>>(ph, NN * HH);
    k_edge1_c0<<<cdiv(ETOT, 256), 256>>>(src, dst);
    k_edge2<true><<<cdiv(ETOT * 32, 256), 256>>>(src, dst, ETOT);
    k_elu<<<cdiv(NN * HH, 256), 256>>>(ph, conv0_b, NN);
    gemm(ph, gru_Wih, gru_bih, pgi, NN, H3, HH, 1);
    gemm(px, gru_Whh, gru_bhh, pgh, NN, H3, HH, 1);
    k_gru<<<cdiv(NN * HH, 256), 256>>>(pgi, pgh, px, NN);

    // ---- remaining atom conv layers (slope 0.01) ----
    for (int l = 0; l < 2; l++) {
        gemm(px, convs_W + (size_t)l * HH * HH, nullptr, phW, NN, HH, HH, 0);
        k_rowdot2<<<cdiv(NN * 32, 256), 256>>>(phW, convs_att_s + l * HH,
                                               convs_att_d + l * HH, ps, pd, NN);
        k_zero<<<cdiv(NN, 256), 256>>>(psum, NN);
        k_zero<<<cdiv(NN * HH, 256), 256>>>(ph, NN * HH);
        k_edge1_plain<<<cdiv(EE, 256), 256>>>(src, dst);
        k_edge2<false><<<cdiv(EE * 32, 256), 256>>>(src, dst, EE);
        k_elu<<<cdiv(NN * HH, 256), 256>>>(ph, convs_b + l * HH, NN);
        gemm(ph, gru_Wih + (size_t)(l + 1) * H3 * HH, gru_bih + (l + 1) * H3, pgi, NN, H3, HH, 1);
        gemm(px, gru_Whh + (size_t)(l + 1) * H3 * HH, gru_bhh + (l + 1) * H3, pgh, NN, H3, HH, 1);
        k_gru<<<cdiv(NN * HH, 256), 256>>>(pgi, pgh, px, NN);
    }

    // ---- molecule readout ----
    k_zero<<<cdiv(GG * HH, 256), 256>>>(pout, GG * HH);
    k_pool<<<cdiv(NN * 48, 256), 256>>>(batch);
    k_relu_inplace<<<cdiv(GG * HH, 256), 256>>>(pout, GG * HH);
    gemm(px, mol_Wsrc, nullptr, phW, NN, HH, HH, 0);
    k_rowdot2<<<cdiv(NN * 32, 256), 256>>>(phW, mol_att_s, nullptr, psmol, nullptr, NN);

    for (int t = 0; t < 2; t++) {
        gemm(pout, mol_Wdst, nullptr, phd, GG, HH, HH, 0);
        k_rowdot2<<<cdiv(GG * 32, 256), 256>>>(phd, mol_att_d, nullptr, pdmol, nullptr, GG);
        k_zero<<<cdiv(GG, 256), 256>>>(pmsum, GG);
        k_zero<<<cdiv(GG * HH, 256), 256>>>(phmol, GG * HH);
        k_mol1<<<cdiv(NN, 256), 256>>>(batch);
        k_mol2<<<cdiv(NN * 32, 256), 256>>>(batch);
        k_elu<<<cdiv(GG * HH, 256), 256>>>(phmol, mol_b, GG);
        gemm(phmol, mgru_Wih, mgru_bih, pgi, GG, H3, HH, 1);
        gemm(pout, mgru_Whh, mgru_bhh, pgh, GG, H3, HH, 1);
        k_gru<<<cdiv(GG * HH, 256), 256>>>(pgi, pgh, pout, GG);
    }

    k_final<<<cdiv(GG * 32, 256), 256>>>(lin2_W, lin2_b, (float*)d_out);
}

// round 4
// speedup vs baseline: 1.9789x; 1.5640x over previous
#include <cuda_runtime.h>
#include <cuda_bf16.h>
#include <math.h>
#include <stdint.h>

#define NN 50000
#define EE 800000
#define CC 64
#define HH 192
#define H3 576
#define EDIM 16
#define GG 2048
#define ETOT (EE + NN)

// ---------------- scratch (device globals; allocation-free rule) ----------------
__device__ __align__(16) float g_x[NN * HH];
__device__ __align__(16) float g_hW[NN * HH];
__device__ __align__(16) float g_h[NN * HH];
__device__ __align__(16) float g_gi[NN * H3];
__device__ __align__(16) float g_gh[NN * H3];
__device__ float g_s[NN];
__device__ float g_d[NN];
__device__ float g_ae[EE];
__device__ float g_ew[ETOT];
__device__ float g_sum[NN];
__device__ float g_v[EDIM];
__device__ float g_loopsum[1];
__device__ __align__(16) float g_out[GG * HH];
__device__ __align__(16) float g_hd[GG * HH];
__device__ __align__(16) float g_hmol[GG * HH];
__device__ float g_smol[NN];
__device__ float g_dmol[GG];
__device__ float g_mew[NN];
__device__ float g_msum[GG];
// bf16x3 split buffers
__device__ __align__(16) __nv_bfloat16 g_a3[(size_t)NN * H3];
__device__ __align__(16) __nv_bfloat16 g_a3b[(size_t)NN * H3];
__device__ __align__(16) __nv_bfloat16 g_b3[(size_t)H3 * H3];
__device__ __align__(16) __nv_bfloat16 g_b3wd[(size_t)HH * H3];
__device__ __align__(16) __nv_bfloat16 g_b3wi[(size_t)H3 * H3];
__device__ __align__(16) __nv_bfloat16 g_b3wh[(size_t)H3 * H3];
__device__ __align__(16) __nv_bfloat16 g_a3m[(size_t)GG * H3];
__device__ __align__(16) __nv_bfloat16 g_a3m2[(size_t)GG * H3];

// ---------------- small helpers ----------------
__device__ __forceinline__ float warp_sum(float v) {
#pragma unroll
    for (int o = 16; o; o >>= 1) v += __shfl_down_sync(0xffffffffu, v, o);
    return v;
}
__device__ __forceinline__ float sigm(float x) { return 1.f / (1.f + expf(-x)); }

__device__ __forceinline__ void red4(float4* p, float4 v) {
    asm volatile("red.global.add.v4.f32 [%0], {%1,%2,%3,%4};"
                 :: "l"(p), "f"(v.x), "f"(v.y), "f"(v.z), "f"(v.w)
                 : "memory");
}

__device__ __forceinline__ uint32_t smem_u32(const void* p) {
    uint32_t a;
    asm("{ .reg .u64 t; cvta.to.shared.u64 t, %1; cvt.u32.u64 %0, t; }" : "=r"(a) : "l"(p));
    return a;
}
__device__ __forceinline__ void cp16(uint32_t s, const void* g) {
    asm volatile("cp.async.cg.shared.global [%0], [%1], 16;" :: "r"(s), "l"(g));
}
__device__ __forceinline__ void ldsm4(uint32_t& r0, uint32_t& r1, uint32_t& r2, uint32_t& r3,
                                      uint32_t addr) {
    asm volatile("ldmatrix.sync.aligned.m8n8.x4.shared.b16 {%0,%1,%2,%3}, [%4];"
                 : "=r"(r0), "=r"(r1), "=r"(r2), "=r"(r3) : "r"(addr));
}
__device__ __forceinline__ void mma16816(float* d, const uint32_t* a, const uint32_t* b) {
    asm volatile(
        "mma.sync.aligned.m16n8k16.row.col.f32.bf16.bf16.f32 "
        "{%0,%1,%2,%3}, {%4,%5,%6,%7}, {%8,%9}, {%0,%1,%2,%3};"
        : "+f"(d[0]), "+f"(d[1]), "+f"(d[2]), "+f"(d[3])
        : "r"(a[0]), "r"(a[1]), "r"(a[2]), "r"(a[3]), "r"(b[0]), "r"(b[1]));
}

// ================= bf16 mma.sync NT GEMM =================
// C[M,Nc] = A3[M,K3] * B3[Nc,K3]^T  (bf16 in, fp32 accum)
// Block tile 128x64xK64, 256 threads, warp grid 4x2 (warp tile 32x32),
// cp.async double buffering, SW128 XOR swizzle (conflict-free ldmatrix).
// EPI: 0 none, 1 +bias, 2 +bias+lrelu(0.01). SPLIT: also write bf16x3 A-mode.
template <int EPI, bool SPLIT>
__global__ void __launch_bounds__(256)
bgemm(const __nv_bfloat16* __restrict__ A3, const __nv_bfloat16* __restrict__ B3,
      const float* __restrict__ bias, float* __restrict__ C,
      __nv_bfloat16* __restrict__ C3, int M, int Nc, int K3) {
    __shared__ __nv_bfloat16 sA[2][128 * 64];
    __shared__ __nv_bfloat16 sB[2][64 * 64];
    const int tid = threadIdx.x;
    const int lane = tid & 31, wid = tid >> 5;
    const int wm = wid & 3, wn = wid >> 2;
    const int row0 = blockIdx.y * 128, col0 = blockIdx.x * 64;
    const uint32_t aB = smem_u32(sA), bB = smem_u32(sB);

    float acc[2][4][4] = {};
    const int nc = K3 >> 6;

    auto issue = [&](int c, int buf) {
        const uint32_t ab = aB + buf * 16384;
        const uint32_t bb = bB + buf * 8192;
#pragma unroll
        for (int q = 0; q < 4; q++) {
            int idx = q * 256 + tid;
            int r = idx >> 3, kc = idx & 7;
            int grow = row0 + r;
            grow = grow < M ? grow : M - 1;
            cp16(ab + (uint32_t)(r * 128 + ((kc * 16) ^ ((r & 7) << 4))),
                 A3 + (size_t)grow * K3 + c * 64 + kc * 8);
        }
#pragma unroll
        for (int q = 0; q < 2; q++) {
            int idx = q * 256 + tid;
            int r = idx >> 3, kc = idx & 7;
            cp16(bb + (uint32_t)(r * 128 + ((kc * 16) ^ ((r & 7) << 4))),
                 B3 + (size_t)(col0 + r) * K3 + c * 64 + kc * 8);
        }
        asm volatile("cp.async.commit_group;" ::: "memory");
    };

    // ldmatrix per-thread row/col components
    const int a_r = wm * 32 + ((lane >> 3) & 1) * 8 + (lane & 7);
    const int a_kb = ((lane >> 4) & 1) * 16;
    const int b_r = wn * 32 + ((lane >> 4) & 1) * 8 + (lane & 7);
    const int b_kb = ((lane >> 3) & 1) * 16;

    issue(0, 0);
    for (int c = 0; c < nc; c++) {
        const int buf = c & 1;
        if (c + 1 < nc) {
            issue(c + 1, buf ^ 1);
            asm volatile("cp.async.wait_group 1;" ::: "memory");
        } else {
            asm volatile("cp.async.wait_group 0;" ::: "memory");
        }
        __syncthreads();
        const uint32_t ab = aB + buf * 16384;
        const uint32_t bb = bB + buf * 8192;
#pragma unroll
        for (int ks = 0; ks < 4; ks++) {
            uint32_t af[2][4], bfr[2][4];
#pragma unroll
            for (int mi = 0; mi < 2; mi++) {
                int r = a_r + mi * 16;
                ldsm4(af[mi][0], af[mi][1], af[mi][2], af[mi][3],
                      ab + (uint32_t)(r * 128 + ((ks * 32 + a_kb) ^ ((r & 7) << 4))));
            }
#pragma unroll
            for (int p = 0; p < 2; p++) {
                int r = b_r + p * 16;
                ldsm4(bfr[p][0], bfr[p][1], bfr[p][2], bfr[p][3],
                      bb + (uint32_t)(r * 128 + ((ks * 32 + b_kb) ^ ((r & 7) << 4))));
            }
#pragma unroll
            for (int mi = 0; mi < 2; mi++)
#pragma unroll
                for (int ni = 0; ni < 4; ni++) {
                    uint32_t b2[2] = {bfr[ni >> 1][(ni & 1) * 2], bfr[ni >> 1][(ni & 1) * 2 + 1]};
                    mma16816(acc[mi][ni], af[mi], b2);
                }
        }
        __syncthreads();
    }

    // epilogue: c0,c1 -> (row = lane/4, col 2(lane%4)); c2,c3 -> row+8
    const int qr = lane >> 2, qc = (lane & 3) * 2;
#pragma unroll
    for (int mi = 0; mi < 2; mi++) {
#pragma unroll
        for (int half = 0; half < 2; half++) {
            int row = row0 + wm * 32 + mi * 16 + half * 8 + qr;
            if (row >= M) continue;
#pragma unroll
            for (int ni = 0; ni < 4; ni++) {
                int cc0 = col0 + wn * 32 + ni * 8 + qc;
                float v0 = acc[mi][ni][half * 2 + 0];
                float v1 = acc[mi][ni][half * 2 + 1];
                if (EPI >= 1) { v0 += bias[cc0]; v1 += bias[cc0 + 1]; }
                if (EPI == 2) {
                    v0 = v0 > 0.f ? v0 : 0.01f * v0;
                    v1 = v1 > 0.f ? v1 : 0.01f * v1;
                }
                *(float2*)(C + (size_t)row * Nc + cc0) = make_float2(v0, v1);
                if (SPLIT) {
                    size_t base = (size_t)row * (3 * Nc) + cc0;
                    __nv_bfloat16 h0 = __float2bfloat16_rn(v0);
                    __nv_bfloat16 l0 = __float2bfloat16_rn(v0 - __bfloat162float(h0));
                    __nv_bfloat16 h1 = __float2bfloat16_rn(v1);
                    __nv_bfloat16 l1 = __float2bfloat16_rn(v1 - __bfloat162float(h1));
                    C3[base] = h0; C3[base + 1] = h1;
                    C3[base + Nc] = h0; C3[base + Nc + 1] = h1;
                    C3[base + 2 * Nc] = l0; C3[base + 2 * Nc + 1] = l1;
                }
            }
        }
    }
}

// ---------------- split kernels ----------------
__global__ void k_splitA(const float* __restrict__ X, __nv_bfloat16* __restrict__ Y,
                         int rows, int K) {
    int idx = blockIdx.x * 256 + threadIdx.x;
    if (idx >= rows * K) return;
    int r = idx / K, j = idx % K;
    float v = X[idx];
    __nv_bfloat16 hi = __float2bfloat16_rn(v);
    __nv_bfloat16 lo = __float2bfloat16_rn(v - __bfloat162float(hi));
    size_t b = (size_t)r * 3 * K + j;
    Y[b] = hi; Y[b + K] = hi; Y[b + 2 * K] = lo;
}
__global__ void k_splitB(const float* __restrict__ X, __nv_bfloat16* __restrict__ Y,
                         int rows, int K) {
    int idx = blockIdx.x * 256 + threadIdx.x;
    if (idx >= rows * K) return;
    int r = idx / K, j = idx % K;
    float v = X[idx];
    __nv_bfloat16 hi = __float2bfloat16_rn(v);
    __nv_bfloat16 lo = __float2bfloat16_rn(v - __bfloat162float(hi));
    size_t b = (size_t)r * 3 * K + j;
    Y[b] = hi; Y[b + K] = lo; Y[b + 2 * K] = hi;
}

__global__ void k_zero(float* p, int n) {
    int i = blockIdx.x * 256 + threadIdx.x;
    if (i < n) p[i] = 0.f;
}

// ---------------- attention / GAT kernels ----------------
__global__ void k_v(const float* __restrict__ We, const float* __restrict__ atte) {
    int j = threadIdx.x;
    if (j < EDIM) {
        float s = 0.f;
        for (int k = 0; k < HH; k++) s += atte[k] * We[k * EDIM + j];
        g_v[j] = s;
    }
    if (j == 0) g_loopsum[0] = 0.f;
}

__global__ void k_ae(const float* __restrict__ attr) {
    __shared__ float sv[EDIM];
    __shared__ float red[256];
    if (threadIdx.x < EDIM) sv[threadIdx.x] = g_v[threadIdx.x];
    __syncthreads();
    int e = blockIdx.x * 256 + threadIdx.x;
    float a = 0.f;
    if (e < EE) {
        const float* p = attr + (size_t)e * EDIM;
#pragma unroll
        for (int j = 0; j < EDIM; j++) a += p[j] * sv[j];
        g_ae[e] = a;
    }
    red[threadIdx.x] = a;
    __syncthreads();
    for (int st = 128; st; st >>= 1) {
        if (threadIdx.x < st) red[threadIdx.x] += red[threadIdx.x + st];
        __syncthreads();
    }
    if (threadIdx.x == 0) atomicAdd(g_loopsum, red[0]);
}

__global__ void k_rowdot2(const float* __restrict__ A, const float* __restrict__ u,
                          const float* __restrict__ w, float* __restrict__ ou,
                          float* __restrict__ ow, int rows) {
    int gw = (blockIdx.x * blockDim.x + threadIdx.x) >> 5;
    int lane = threadIdx.x & 31;
    if (gw >= rows) return;
    const float* a = A + (size_t)gw * HH;
    float s1 = 0.f, s2 = 0.f;
    for (int k = lane; k < HH; k += 32) {
        float v = a[k];
        s1 += v * u[k];
        if (w) s2 += v * w[k];
    }
    s1 = warp_sum(s1);
    if (w) s2 = warp_sum(s2);
    if (lane == 0) {
        ou[gw] = s1;
        if (w) ow[gw] = s2;
    }
}

__global__ void k_edge1_c0(const int* __restrict__ src, const int* __restrict__ dst) {
    int idx = blockIdx.x * 256 + threadIdx.x;
    if (idx >= ETOT) return;
    int dd;
    float a;
    if (idx < EE) {
        int ss = src[idx];
        dd = dst[idx];
        a = g_s[ss] + g_d[dd] + g_ae[idx];
    } else {
        int i = idx - EE;
        dd = i;
        a = g_s[i] + g_d[i] + g_loopsum[0] * (1.0f / EE);
    }
    a = a >= 0.f ? a : 0.2f * a;
    float e = expf(a);
    g_ew[idx] = e;
    atomicAdd(&g_sum[dd], e);
}

__global__ void k_edge1_plain(const int* __restrict__ src, const int* __restrict__ dst) {
    int idx = blockIdx.x * 256 + threadIdx.x;
    if (idx >= EE) return;
    float a = g_s[src[idx]] + g_d[dst[idx]];
    a = a >= 0.f ? a : 0.01f * a;
    float e = expf(a);
    g_ew[idx] = e;
    atomicAdd(&g_sum[dst[idx]], e);
}

template <bool SELF>
__global__ void k_edge2(const int* __restrict__ src, const int* __restrict__ dst, int etot) {
    int gw = (blockIdx.x * blockDim.x + threadIdx.x) >> 5;
    int lane = threadIdx.x & 31;
    if (gw >= etot) return;
    int ss = 0, dd = 0;
    float w = 0.f;
    if (lane == 0) {
        if (SELF && gw >= EE) {
            ss = dd = gw - EE;
        } else {
            ss = src[gw];
            dd = dst[gw];
        }
        w = g_ew[gw] / (g_sum[dd] + 1e-16f);
    }
    ss = __shfl_sync(0xffffffffu, ss, 0);
    dd = __shfl_sync(0xffffffffu, dd, 0);
    w = __shfl_sync(0xffffffffu, w, 0);
    const float4* hs = (const float4*)(g_hW + (size_t)ss * HH);
    float4* o = (float4*)(g_h + (size_t)dd * HH);
    float4 v = hs[lane];
    red4(o + lane, make_float4(w * v.x, w * v.y, w * v.z, w * v.w));
    if (lane < 16) {
        float4 v2 = hs[lane + 32];
        red4(o + lane + 32, make_float4(w * v2.x, w * v2.y, w * v2.z, w * v2.w));
    }
}

// ELU(h + b) -> bf16x3 split (A-mode)
__global__ void k_elu_split(const float* __restrict__ h, const float* __restrict__ b,
                            __nv_bfloat16* __restrict__ out3, int rows) {
    int idx = blockIdx.x * 256 + threadIdx.x;
    if (idx >= rows * HH) return;
    int i = idx / HH, j = idx % HH;
    float v = h[idx] + b[j];
    v = v > 0.f ? v : expm1f(v);
    __nv_bfloat16 hi = __float2bfloat16_rn(v);
    __nv_bfloat16 lo = __float2bfloat16_rn(v - __bfloat162float(hi));
    size_t o = (size_t)i * H3 + j;
    out3[o] = hi; out3[o + HH] = hi; out3[o + 2 * HH] = lo;
}

// GRU + relu; writes x fp32 and bf16x3 split
__global__ void k_gru(const float* __restrict__ gi, const float* __restrict__ gh,
                      float* __restrict__ x, __nv_bfloat16* __restrict__ out3, int rows) {
    int idx = blockIdx.x * 256 + threadIdx.x;
    if (idx >= rows * HH) return;
    int i = idx / HH, j = idx % HH;
    const float* a = gi + (size_t)i * H3;
    const float* b = gh + (size_t)i * H3;
    float r = sigm(a[j] + b[j]);
    float z = sigm(a[HH + j] + b[HH + j]);
    float n = tanhf(a[2 * HH + j] + r * b[2 * HH + j]);
    float o = (1.f - z) * n + z * x[idx];
    o = o > 0.f ? o : 0.f;
    x[idx] = o;
    __nv_bfloat16 hi = __float2bfloat16_rn(o);
    __nv_bfloat16 lo = __float2bfloat16_rn(o - __bfloat162float(hi));
    size_t t = (size_t)i * H3 + j;
    out3[t] = hi; out3[t + HH] = hi; out3[t + 2 * HH] = lo;
}

__global__ void k_pool(const int* __restrict__ batch) {
    int idx = blockIdx.x * 256 + threadIdx.x;
    if (idx >= NN * 48) return;
    int i = idx / 48, j = idx % 48;
    float4 v = ((const float4*)(g_x + (size_t)i * HH))[j];
    red4(((float4*)(g_out + (size_t)batch[i] * HH)) + j, v);
}

// relu(out) in place + bf16x3 split
__global__ void k_relu_split(float* __restrict__ p, __nv_bfloat16* __restrict__ out3, int rows) {
    int idx = blockIdx.x * 256 + threadIdx.x;
    if (idx >= rows * HH) return;
    int i = idx / HH, j = idx % HH;
    float o = p[idx];
    o = o > 0.f ? o : 0.f;
    p[idx] = o;
    __nv_bfloat16 hi = __float2bfloat16_rn(o);
    __nv_bfloat16 lo = __float2bfloat16_rn(o - __bfloat162float(hi));
    size_t t = (size_t)i * H3 + j;
    out3[t] = hi; out3[t + HH] = hi; out3[t + 2 * HH] = lo;
}

__global__ void k_mol1(const int* __restrict__ batch) {
    int i = blockIdx.x * 256 + threadIdx.x;
    if (i >= NN) return;
    float a = g_smol[i] + g_dmol[batch[i]];
    a = a >= 0.f ? a : 0.01f * a;
    float e = expf(a);
    g_mew[i] = e;
    atomicAdd(&g_msum[batch[i]], e);
}

__global__ void k_mol2(const int* __restrict__ batch) {
    int gw = (blockIdx.x * blockDim.x + threadIdx.x) >> 5;
    int lane = threadIdx.x & 31;
    if (gw >= NN) return;
    int b = 0;
    float w = 0.f;
    if (lane == 0) {
        b = batch[gw];
        w = g_mew[gw] / (g_msum[b] + 1e-16f);
    }
    b = __shfl_sync(0xffffffffu, b, 0);
    w = __shfl_sync(0xffffffffu, w, 0);
    const float4* hs = (const float4*)(g_hW + (size_t)gw * HH);
    float4* o = (float4*)(g_hmol + (size_t)b * HH);
    float4 v = hs[lane];
    red4(o + lane, make_float4(w * v.x, w * v.y, w * v.z, w * v.w));
    if (lane < 16) {
        float4 v2 = hs[lane + 32];
        red4(o + lane + 32, make_float4(w * v2.x, w * v2.y, w * v2.z, w * v2.w));
    }
}

__global__ void k_final(const float* __restrict__ W, const float* __restrict__ b,
                        float* __restrict__ out) {
    int gw = (blockIdx.x * blockDim.x + threadIdx.x) >> 5;
    int lane = threadIdx.x & 31;
    if (gw >= GG) return;
    float s = 0.f;
    for (int k = lane; k < HH; k += 32) s += g_out[gw * HH + k] * W[k];
    s = warp_sum(s);
    if (lane == 0) out[gw] = s + b[0];
}

// ---------------- host ----------------
static inline int cdiv(int a, int b) { return (a + b - 1) / b; }

extern "C" void kernel_launch(void* const* d_in, const int* in_sizes, int n_in,
                              void* d_out, int out_size) {
    const float* x_in = (const float*)d_in[0];
    const int* eidx = (const int*)d_in[1];
    const float* eattr = (const float*)d_in[2];
    const int* batch = (const int*)d_in[3];
    const float* lin1_W = (const float*)d_in[4];
    const float* lin1_b = (const float*)d_in[5];
    const float* conv0_W = (const float*)d_in[6];
    const float* conv0_att_s = (const float*)d_in[7];
    const float* conv0_att_d = (const float*)d_in[8];
    const float* conv0_We = (const float*)d_in[9];
    const float* conv0_att_e = (const float*)d_in[10];
    const float* conv0_b = (const float*)d_in[11];
    const float* convs_W = (const float*)d_in[12];
    const float* convs_att_s = (const float*)d_in[13];
    const float* convs_att_d = (const float*)d_in[14];
    const float* convs_b = (const float*)d_in[15];
    const float* gru_Wih = (const float*)d_in[16];
    const float* gru_Whh = (const float*)d_in[17];
    const float* gru_bih = (const float*)d_in[18];
    const float* gru_bhh = (const float*)d_in[19];
    const float* mol_Wsrc = (const float*)d_in[20];
    const float* mol_Wdst = (const float*)d_in[21];
    const float* mol_att_s = (const float*)d_in[22];
    const float* mol_att_d = (const float*)d_in[23];
    const float* mol_b = (const float*)d_in[24];
    const float* mgru_Wih = (const float*)d_in[25];
    const float* mgru_Whh = (const float*)d_in[26];
    const float* mgru_bih = (const float*)d_in[27];
    const float* mgru_bhh = (const float*)d_in[28];
    const float* lin2_W = (const float*)d_in[29];
    const float* lin2_b = (const float*)d_in[30];

    const int* src = eidx;
    const int* dst = eidx + EE;

    float *px, *phW, *ph, *pgi, *pgh, *ps, *pd, *psum, *pout, *phd, *phmol, *psmol, *pdmol, *pmsum;
    cudaGetSymbolAddress((void**)&px, g_x);
    cudaGetSymbolAddress((void**)&phW, g_hW);
    cudaGetSymbolAddress((void**)&ph, g_h);
    cudaGetSymbolAddress((void**)&pgi, g_gi);
    cudaGetSymbolAddress((void**)&pgh, g_gh);
    cudaGetSymbolAddress((void**)&ps, g_s);
    cudaGetSymbolAddress((void**)&pd, g_d);
    cudaGetSymbolAddress((void**)&psum, g_sum);
    cudaGetSymbolAddress((void**)&pout, g_out);
    cudaGetSymbolAddress((void**)&phd, g_hd);
    cudaGetSymbolAddress((void**)&phmol, g_hmol);
    cudaGetSymbolAddress((void**)&psmol, g_smol);
    cudaGetSymbolAddress((void**)&pdmol, g_dmol);
    cudaGetSymbolAddress((void**)&pmsum, g_msum);
    __nv_bfloat16 *a3, *a3b, *b3, *b3wd, *b3wi, *b3wh, *a3m, *a3m2;
    cudaGetSymbolAddress((void**)&a3, g_a3);
    cudaGetSymbolAddress((void**)&a3b, g_a3b);
    cudaGetSymbolAddress((void**)&b3, g_b3);
    cudaGetSymbolAddress((void**)&b3wd, g_b3wd);
    cudaGetSymbolAddress((void**)&b3wi, g_b3wi);
    cudaGetSymbolAddress((void**)&b3wh, g_b3wh);
    cudaGetSymbolAddress((void**)&a3m, g_a3m);
    cudaGetSymbolAddress((void**)&a3m2, g_a3m2);

    auto splitB = [&](const float* W, __nv_bfloat16* Y, int R, int K) {
        k_splitB<<<cdiv(R * K, 256), 256>>>(W, Y, R, K);
    };
    auto bg0 = [&](const __nv_bfloat16* A, const __nv_bfloat16* B, float* C, int M, int Nc, int K3) {
        bgemm<0, false><<<dim3(Nc / 64, cdiv(M, 128)), 256>>>(A, B, nullptr, C, nullptr, M, Nc, K3);
    };
    auto bg1 = [&](const __nv_bfloat16* A, const __nv_bfloat16* B, const float* bias, float* C,
                   int M, int Nc, int K3) {
        bgemm<1, false><<<dim3(Nc / 64, cdiv(M, 128)), 256>>>(A, B, bias, C, nullptr, M, Nc, K3);
    };

    // ---- lin1: px = lrelu(x_in @ lin1_W^T + b); fused split(px)->a3 ----
    k_splitA<<<cdiv(NN * CC, 256), 256>>>(x_in, a3b, NN, CC);
    splitB(lin1_W, b3, HH, CC);
    bgemm<2, true><<<dim3(HH / 64, cdiv(NN, 128)), 256>>>(a3b, b3, lin1_b, px, a3, NN, HH, 3 * CC);

    // ---- conv0 (edge features + self loops, slope 0.2) ----
    k_v<<<1, 32>>>(conv0_We, conv0_att_e);
    k_ae<<<cdiv(EE, 256), 256>>>(eattr);
    splitB(conv0_W, b3, HH, HH);
    bg0(a3, b3, phW, NN, HH, H3);
    k_rowdot2<<<cdiv(NN * 32, 256), 256>>>(phW, conv0_att_s, conv0_att_d, ps, pd, NN);
    k_zero<<<cdiv(NN, 256), 256>>>(psum, NN);
    k_zero<<<cdiv(NN * HH, 256), 256>>>(ph, NN * HH);
    k_edge1_c0<<<cdiv(ETOT, 256), 256>>>(src, dst);
    k_edge2<true><<<cdiv(ETOT * 32, 256), 256>>>(src, dst, ETOT);
    splitB(gru_Whh, b3wh, H3, HH);
    bg1(a3, b3wh, gru_bhh, pgh, NN, H3, H3);
    k_elu_split<<<cdiv(NN * HH, 256), 256>>>(ph, conv0_b, a3b, NN);
    splitB(gru_Wih, b3, H3, HH);
    bg1(a3b, b3, gru_bih, pgi, NN, H3, H3);
    k_gru<<<cdiv(NN * HH, 256), 256>>>(pgi, pgh, px, a3, NN);

    // ---- remaining atom conv layers (slope 0.01) ----
    for (int l = 0; l < 2; l++) {
        splitB(convs_W + (size_t)l * HH * HH, b3, HH, HH);
        bg0(a3, b3, phW, NN, HH, H3);
        k_rowdot2<<<cdiv(NN * 32, 256), 256>>>(phW, convs_att_s + l * HH,
                                               convs_att_d + l * HH, ps, pd, NN);
        k_zero<<<cdiv(NN, 256), 256>>>(psum, NN);
        k_zero<<<cdiv(NN * HH, 256), 256>>>(ph, NN * HH);
        k_edge1_plain<<<cdiv(EE, 256), 256>>>(src, dst);
        k_edge2<false><<<cdiv(EE * 32, 256), 256>>>(src, dst, EE);
        splitB(gru_Whh + (size_t)(l + 1) * H3 * HH, b3wh, H3, HH);
        bg1(a3, b3wh, gru_bhh + (l + 1) * H3, pgh, NN, H3, H3);
        k_elu_split<<<cdiv(NN * HH, 256), 256>>>(ph, convs_b + l * HH, a3b, NN);
        splitB(gru_Wih + (size_t)(l + 1) * H3 * HH, b3, H3, HH);
        bg1(a3b, b3, gru_bih + (l + 1) * H3, pgi, NN, H3, H3);
        k_gru<<<cdiv(NN * HH, 256), 256>>>(pgi, pgh, px, a3, NN);
    }

    // ---- molecule readout ----
    k_zero<<<cdiv(GG * HH, 256), 256>>>(pout, GG * HH);
    k_pool<<<cdiv(NN * 48, 256), 256>>>(batch);
    k_relu_split<<<cdiv(GG * HH, 256), 256>>>(pout, a3m, GG);
    splitB(mol_Wsrc, b3, HH, HH);
    bg0(a3, b3, phW, NN, HH, H3);  // hs in g_hW
    k_rowdot2<<<cdiv(NN * 32, 256), 256>>>(phW, mol_att_s, nullptr, psmol, nullptr, NN);
    splitB(mol_Wdst, b3wd, HH, HH);
    splitB(mgru_Wih, b3wi, H3, HH);
    splitB(mgru_Whh, b3wh, H3, HH);

    for (int t = 0; t < 2; t++) {
        bg0(a3m, b3wd, phd, GG, HH, H3);
        k_rowdot2<<<cdiv(GG * 32, 256), 256>>>(phd, mol_att_d, nullptr, pdmol, nullptr, GG);
        k_zero<<<cdiv(GG, 256), 256>>>(pmsum, GG);
        k_zero<<<cdiv(GG * HH, 256), 256>>>(phmol, GG * HH);
        k_mol1<<<cdiv(NN, 256), 256>>>(batch);
        k_mol2<<<cdiv(NN * 32, 256), 256>>>(batch);
        k_elu_split<<<cdiv(GG * HH, 256), 256>>>(phmol, mol_b, a3m2, GG);
        bg1(a3m2, b3wi, mgru_bih, pgi, GG, H3, H3);
        bg1(a3m, b3wh, mgru_bhh, pgh, GG, H3, H3);
        k_gru<<<cdiv(GG * HH, 256), 256>>>(pgi, pgh, pout, a3m, GG);
    }

    k_final<<<cdiv(GG * 32, 256), 256>>>(lin2_W, lin2_b, (float*)d_out);
}